// round 6
// baseline (speedup 1.0000x reference)
#include <cuda_runtime.h>
#include <cuda_bf16.h>
#include <cstdint>

// CrossSetNorm: x[B=2048, S=328, D=256] f32, mask[B,S] int32 (nonzero = dead).
// R6: persistent CTAs (grid=296, 2/SM), double-buffered cp.async prefetch.
// Tile = (batch, segment, feature-quarter): max 200 rows x 64 feats = 50KB.

#define B_TOT   2048
#define S_TOT   328
#define D_FEAT  256
#define D_QTR   64
#define S_OBJ   128
#define S_ROAD  200
#define NTHREADS 512
#define N_TILES (B_TOT * 2 * 4)   // 16384

// Shared memory layout (float slots), per CTA:
//   [0, 25600)        data buffers: 2 x (200*64) floats (50KB each)
//   [25600, 26112)    r1 fold scratch [8][64]
//   [26112, 26624)    r2 fold scratch [8][64]
//   [26624, 26688)    a[64]
//   [26688, 26752)    c[64]
//   [26752, 27152)    alive raw ints: 2 x 200
//   [27152]           count
#define OFF_DATA   0
#define BUF_FLOATS 12800
#define OFF_R1     25600
#define OFF_R2     26112
#define OFF_A      26624
#define OFF_C      26688
#define OFF_ALIVE  26752
#define OFF_CNT    27152
#define SMEM_FLOATS 27156
#define SMEM_BYTES (SMEM_FLOATS * 4)

__device__ __forceinline__ void cp_async16(uint32_t smem_addr, const void* gptr) {
    asm volatile("cp.async.cg.shared.global [%0], [%1], 16;\n"
                 :: "r"(smem_addr), "l"(gptr) : "memory");
}

struct TileInfo {
    int S, fo;
    size_t row_base;
};

__device__ __forceinline__ TileInfo tile_info(int t) {
    TileInfo ti;
    int quarter = t & 3;
    int seg     = (t >> 2) & 1;
    int b       = t >> 3;
    ti.S  = seg ? S_ROAD : S_OBJ;
    ti.fo = quarter * D_QTR;
    ti.row_base = (size_t)b * S_TOT + (seg ? S_OBJ : 0);
    return ti;
}

__device__ __forceinline__ void prefetch_tile(const float* __restrict__ x,
                                              const int* __restrict__ mask,
                                              int t, int buf,
                                              float* smem, int tid)
{
    TileInfo ti = tile_info(t);
    const float* xin = x + ti.row_base * D_FEAT + ti.fo;
    const int*   m   = mask + ti.row_base;

    const int tx = tid & 15;
    const int ty = tid >> 4;

    uint32_t sdata = (uint32_t)__cvta_generic_to_shared(smem + OFF_DATA + buf * BUF_FLOATS);
    #pragma unroll
    for (int s = ty; s < S_ROAD; s += 32) {
        if (s < ti.S) {
            cp_async16(sdata + (uint32_t)(s * 16 + tx) * 16,
                       xin + (size_t)s * D_FEAT + tx * 4);
        }
    }
    uint32_t salive = (uint32_t)__cvta_generic_to_shared(smem + OFF_ALIVE + buf * 200);
    int nm = ti.S >> 2;              // 16B chunks (S divisible by 4)
    if (tid < nm) cp_async16(salive + (uint32_t)tid * 16, m + tid * 4);
}

__global__ void __launch_bounds__(NTHREADS, 2)
cross_set_norm_kernel(const float* __restrict__ x,
                      const int* __restrict__ mask,
                      const float* __restrict__ w_obj,
                      const float* __restrict__ b_obj,
                      const float* __restrict__ w_road,
                      const float* __restrict__ b_road,
                      float* __restrict__ out)
{
    extern __shared__ float smem[];
    const int tid = threadIdx.x;
    const int tx  = tid & 15;    // float4 column within quarter
    const int ty  = tid >> 4;    // 0..31 row group
    const int lane = tid & 31;
    const int wrp  = tid >> 5;   // 0..15
    const int G = gridDim.x;

    int t = blockIdx.x;
    if (t < N_TILES) prefetch_tile(x, mask, t, 0, smem, tid);
    asm volatile("cp.async.commit_group;\n" ::: "memory");

    int buf = 0;
    for (; t < N_TILES; t += G, buf ^= 1) {
        const int nt = t + G;
        const bool has_next = nt < N_TILES;
        if (has_next) {
            prefetch_tile(x, mask, nt, buf ^ 1, smem, tid);
            asm volatile("cp.async.commit_group;\n" ::: "memory");
            asm volatile("cp.async.wait_group 1;\n" ::: "memory");
        } else {
            asm volatile("cp.async.wait_group 0;\n" ::: "memory");
        }
        __syncthreads();

        const TileInfo ti = tile_info(t);
        const int S = ti.S;
        const int seg = (t >> 2) & 1;
        const float* __restrict__ wseg = (seg ? w_road : w_obj) + ti.fo;
        const float* __restrict__ bseg = (seg ? b_road : b_obj) + ti.fo;

        float4* datav = reinterpret_cast<float4*>(smem + OFF_DATA + buf * BUF_FLOATS);
        const int* aint = reinterpret_cast<const int*>(smem + OFF_ALIVE) + buf * 200;

        // ---- sum pass: v = x * alive --------------------------------
        float s1x = 0.f, s1y = 0.f, s1z = 0.f, s1w = 0.f;
        float s2x = 0.f, s2y = 0.f, s2z = 0.f, s2w = 0.f;
        #pragma unroll 4
        for (int s = ty; s < S; s += 32) {
            float al = aint[s] ? 0.0f : 1.0f;
            float4 v = datav[s * 16 + tx];
            v.x *= al; v.y *= al; v.z *= al; v.w *= al;
            s1x += v.x; s1y += v.y; s1z += v.z; s1w += v.w;
            s2x += v.x * v.x; s2y += v.y * v.y; s2z += v.z * v.z; s2w += v.w * v.w;
        }

        // intra-warp fold: lane l += lane l+16 (same tx, adjacent row group)
        const unsigned FULL = 0xffffffffu;
        s1x += __shfl_down_sync(FULL, s1x, 16); s1y += __shfl_down_sync(FULL, s1y, 16);
        s1z += __shfl_down_sync(FULL, s1z, 16); s1w += __shfl_down_sync(FULL, s1w, 16);
        s2x += __shfl_down_sync(FULL, s2x, 16); s2y += __shfl_down_sync(FULL, s2y, 16);
        s2z += __shfl_down_sync(FULL, s2z, 16); s2w += __shfl_down_sync(FULL, s2w, 16);

        // fold 16 warps -> 8 rows in smem
        float4* r1 = reinterpret_cast<float4*>(smem + OFF_R1);
        float4* r2 = reinterpret_cast<float4*>(smem + OFF_R2);
        if (wrp >= 8 && lane < 16) {
            r1[(wrp - 8) * 16 + lane] = make_float4(s1x, s1y, s1z, s1w);
            r2[(wrp - 8) * 16 + lane] = make_float4(s2x, s2y, s2z, s2w);
        }
        __syncthreads();
        if (wrp < 8 && lane < 16) {
            float4 p1 = r1[wrp * 16 + lane];
            float4 p2 = r2[wrp * 16 + lane];
            p1.x += s1x; p1.y += s1y; p1.z += s1z; p1.w += s1w;
            p2.x += s2x; p2.y += s2y; p2.z += s2z; p2.w += s2w;
            r1[wrp * 16 + lane] = p1;
            r2[wrp * 16 + lane] = p2;
        }
        __syncthreads();

        // ---- final per-feature reduce + count -----------------------
        float S1 = 0.f, S2 = 0.f;
        if (tid < D_QTR) {
            #pragma unroll
            for (int k = 0; k < 8; k++) {
                S1 += smem[OFF_R1 + k * D_QTR + tid];
                S2 += smem[OFF_R2 + k * D_QTR + tid];
            }
        } else if (tid < D_QTR + 32) {
            float c = 0.f;
            for (int s = lane; s < S; s += 32) c += (aint[s] ? 0.0f : 1.0f);
            #pragma unroll
            for (int o = 16; o > 0; o >>= 1) c += __shfl_down_sync(FULL, c, o);
            if (lane == 0) smem[OFF_CNT] = c;
        }
        __syncthreads();

        if (tid < D_QTR) {
            float cnt = smem[OFF_CNT];
            float cc  = fmaxf(cnt, 1.0f);
            bool  ok  = cnt > 1.0f;
            float mean = ok ? (S1 / cc) : S1;
            float var  = (S2 - 2.0f * mean * S1 + (float)S * mean * mean) / cc;
            float inv  = ok ? rsqrtf(var + 1e-6f) : 1.0f;
            float a = inv * wseg[tid];
            float c = bseg[tid] - mean * a;
            smem[OFF_A + tid] = a;
            smem[OFF_C + tid] = c;
        }
        __syncthreads();

        // ---- epilogue: out = x*(al*a) + c ---------------------------
        const int d0 = tx * 4;
        float a0 = smem[OFF_A + d0 + 0], a1 = smem[OFF_A + d0 + 1];
        float a2 = smem[OFF_A + d0 + 2], a3 = smem[OFF_A + d0 + 3];
        float c0 = smem[OFF_C + d0 + 0], c1 = smem[OFF_C + d0 + 1];
        float c2 = smem[OFF_C + d0 + 2], c3 = smem[OFF_C + d0 + 3];

        float* outp = out + ti.row_base * D_FEAT + ti.fo;
        #pragma unroll 4
        for (int s = ty; s < S; s += 32) {
            float al = aint[s] ? 0.0f : 1.0f;
            float4 v = datav[s * 16 + tx];
            float4 o;
            o.x = fmaf(v.x, al * a0, c0);
            o.y = fmaf(v.y, al * a1, c1);
            o.z = fmaf(v.z, al * a2, c2);
            o.w = fmaf(v.w, al * a3, c3);
            float4* orow = reinterpret_cast<float4*>(outp + (size_t)s * D_FEAT);
            orow[tx] = o;
        }

        // all threads done reading this iteration's buffers before the next
        // iteration's prefetch overwrites the opposite parity
        __syncthreads();
    }
}

extern "C" void kernel_launch(void* const* d_in, const int* in_sizes, int n_in,
                              void* d_out, int out_size)
{
    const float* x      = (const float*)d_in[0];
    const int*   mask   = (const int*)d_in[1];
    const float* w_obj  = (const float*)d_in[2];
    const float* b_obj  = (const float*)d_in[3];
    const float* w_road = (const float*)d_in[4];
    const float* b_road = (const float*)d_in[5];
    float* out = (float*)d_out;

    cudaFuncSetAttribute(cross_set_norm_kernel,
                         cudaFuncAttributeMaxDynamicSharedMemorySize, SMEM_BYTES);

    dim3 grid(296);   // 2 CTAs x 148 SMs, persistent
    dim3 block(NTHREADS);
    cross_set_norm_kernel<<<grid, block, SMEM_BYTES>>>(
        x, mask, w_obj, b_obj, w_road, b_road, out);
}

// round 7
// speedup vs baseline: 1.2215x; 1.2215x over previous
#include <cuda_runtime.h>
#include <cuda_bf16.h>
#include <cstdint>

// CrossSetNorm: x[B=2048, S=328, D=256] f32, mask[B,S] int32 (nonzero = dead).
// R7: non-persistent (one tile per CTA, like R5) but quarter-width tiles so
// 4 CTAs fit per SM. cp.async stages raw x + mask; mask applied algebraically.
// Tile = (batch, segment, feature-quarter): max 200 rows x 64 feats = 50KB.

#define B_TOT   2048
#define S_TOT   328
#define D_FEAT  256
#define D_QTR   64
#define S_OBJ   128
#define S_ROAD  200
#define NTHREADS 512

// Shared memory layout (float slots), per CTA:
//   [0, 12800)        raw x tile (200*64 max)
//   [12800, 13312)    r1 fold scratch [8][64]
//   [13312, 13824)    r2 fold scratch [8][64]
//   [13824, 13888)    a[64]
//   [13888, 13952)    c[64]
//   [13952, 14152)    mask raw ints (200)
//   [14152]           count
#define OFF_DATA   0
#define OFF_R1     12800
#define OFF_R2     13312
#define OFF_A      13824
#define OFF_C      13888
#define OFF_ALIVE  13952
#define OFF_CNT    14152
#define SMEM_FLOATS 14156
#define SMEM_BYTES (SMEM_FLOATS * 4)   // 56624 B; x4 CTAs = 226.5KB/SM

__device__ __forceinline__ void cp_async16(uint32_t smem_addr, const void* gptr) {
    asm volatile("cp.async.cg.shared.global [%0], [%1], 16;\n"
                 :: "r"(smem_addr), "l"(gptr) : "memory");
}

__global__ void __launch_bounds__(NTHREADS, 4)
cross_set_norm_kernel(const float* __restrict__ x,
                      const int* __restrict__ mask,
                      const float* __restrict__ w_obj,
                      const float* __restrict__ b_obj,
                      const float* __restrict__ w_road,
                      const float* __restrict__ b_road,
                      float* __restrict__ out)
{
    extern __shared__ float smem[];

    const int bid     = blockIdx.x;
    const int quarter = bid & 3;          // feature quarter
    const int seg     = (bid >> 2) & 1;   // 0 = obj, 1 = road
    const int b       = bid >> 3;

    const int S   = seg ? S_ROAD : S_OBJ;
    const int off = seg ? S_OBJ : 0;
    const int fo  = quarter * D_QTR;
    const float* __restrict__ wseg = (seg ? w_road : w_obj) + fo;
    const float* __restrict__ bseg = (seg ? b_road : b_obj) + fo;

    const size_t row_base = ((size_t)b * S_TOT + off);
    const float* xin  = x    + row_base * D_FEAT + fo;
    float*       outp = out  + row_base * D_FEAT + fo;
    const int*   m    = mask + row_base;

    const int tid  = threadIdx.x;
    const int tx   = tid & 15;   // float4 column: features [4*tx, 4*tx+4) in quarter
    const int ty   = tid >> 4;   // 0..31 row group
    const int lane = tid & 31;
    const int wrp  = tid >> 5;   // 0..15
    const unsigned FULL = 0xffffffffu;

    // ---- Phase A: fire whole tile (raw x) + mask via cp.async ---------
    {
        uint32_t sdata = (uint32_t)__cvta_generic_to_shared(smem + OFF_DATA);
        #pragma unroll
        for (int s = ty; s < S_ROAD; s += 32) {
            if (s < S) {
                cp_async16(sdata + (uint32_t)(s * 16 + tx) * 16,
                           xin + (size_t)s * D_FEAT + tx * 4);
            }
        }
        uint32_t salive = (uint32_t)__cvta_generic_to_shared(smem + OFF_ALIVE);
        if (tid < (S >> 2)) cp_async16(salive + (uint32_t)tid * 16, m + tid * 4);
        asm volatile("cp.async.commit_group;\n" ::: "memory");
        asm volatile("cp.async.wait_group 0;\n" ::: "memory");
    }
    __syncthreads();

    float4* datav = reinterpret_cast<float4*>(smem + OFF_DATA);
    const int* aint = reinterpret_cast<const int*>(smem + OFF_ALIVE);

    // ---- Phase B: sum pass from smem (v = x * alive) ------------------
    float s1x = 0.f, s1y = 0.f, s1z = 0.f, s1w = 0.f;
    float s2x = 0.f, s2y = 0.f, s2z = 0.f, s2w = 0.f;
    #pragma unroll 4
    for (int s = ty; s < S; s += 32) {
        float al = aint[s] ? 0.0f : 1.0f;
        float4 v = datav[s * 16 + tx];
        v.x *= al; v.y *= al; v.z *= al; v.w *= al;
        s1x += v.x; s1y += v.y; s1z += v.z; s1w += v.w;
        s2x += v.x * v.x; s2y += v.y * v.y; s2z += v.z * v.z; s2w += v.w * v.w;
    }

    // intra-warp fold: lane l += lane l+16 (same tx, adjacent row group)
    s1x += __shfl_down_sync(FULL, s1x, 16); s1y += __shfl_down_sync(FULL, s1y, 16);
    s1z += __shfl_down_sync(FULL, s1z, 16); s1w += __shfl_down_sync(FULL, s1w, 16);
    s2x += __shfl_down_sync(FULL, s2x, 16); s2y += __shfl_down_sync(FULL, s2y, 16);
    s2z += __shfl_down_sync(FULL, s2z, 16); s2w += __shfl_down_sync(FULL, s2w, 16);

    // fold 16 warps -> 8 rows in smem
    float4* r1 = reinterpret_cast<float4*>(smem + OFF_R1);
    float4* r2 = reinterpret_cast<float4*>(smem + OFF_R2);
    if (wrp >= 8 && lane < 16) {
        r1[(wrp - 8) * 16 + lane] = make_float4(s1x, s1y, s1z, s1w);
        r2[(wrp - 8) * 16 + lane] = make_float4(s2x, s2y, s2z, s2w);
    }
    __syncthreads();
    if (wrp < 8 && lane < 16) {
        float4 p1 = r1[wrp * 16 + lane];
        float4 p2 = r2[wrp * 16 + lane];
        p1.x += s1x; p1.y += s1y; p1.z += s1z; p1.w += s1w;
        p2.x += s2x; p2.y += s2y; p2.z += s2z; p2.w += s2w;
        r1[wrp * 16 + lane] = p1;
        r2[wrp * 16 + lane] = p2;
    }
    __syncthreads();

    // ---- Phase C: final per-feature reduce + count --------------------
    float S1 = 0.f, S2 = 0.f;
    if (tid < D_QTR) {
        #pragma unroll
        for (int k = 0; k < 8; k++) {
            S1 += smem[OFF_R1 + k * D_QTR + tid];
            S2 += smem[OFF_R2 + k * D_QTR + tid];
        }
    } else if (tid < D_QTR + 32) {
        float c = 0.f;
        for (int s = lane; s < S; s += 32) c += (aint[s] ? 0.0f : 1.0f);
        #pragma unroll
        for (int o = 16; o > 0; o >>= 1) c += __shfl_down_sync(FULL, c, o);
        if (lane == 0) smem[OFF_CNT] = c;
    }
    __syncthreads();

    if (tid < D_QTR) {
        float cnt = smem[OFF_CNT];
        float cc  = fmaxf(cnt, 1.0f);
        bool  ok  = cnt > 1.0f;
        float mean = ok ? (S1 / cc) : S1;
        float var  = (S2 - 2.0f * mean * S1 + (float)S * mean * mean) / cc;
        float inv  = ok ? rsqrtf(var + 1e-6f) : 1.0f;
        float a = inv * wseg[tid];
        float c = bseg[tid] - mean * a;
        smem[OFF_A + tid] = a;
        smem[OFF_C + tid] = c;
    }
    __syncthreads();

    // ---- Phase D: fused epilogue; out = x*(al*a) + c ------------------
    const int d0 = tx * 4;
    float a0 = smem[OFF_A + d0 + 0], a1 = smem[OFF_A + d0 + 1];
    float a2 = smem[OFF_A + d0 + 2], a3 = smem[OFF_A + d0 + 3];
    float c0 = smem[OFF_C + d0 + 0], c1 = smem[OFF_C + d0 + 1];
    float c2 = smem[OFF_C + d0 + 2], c3 = smem[OFF_C + d0 + 3];

    #pragma unroll 4
    for (int s = ty; s < S; s += 32) {
        float al = aint[s] ? 0.0f : 1.0f;
        float4 v = datav[s * 16 + tx];
        float4 o;
        o.x = fmaf(v.x, al * a0, c0);
        o.y = fmaf(v.y, al * a1, c1);
        o.z = fmaf(v.z, al * a2, c2);
        o.w = fmaf(v.w, al * a3, c3);
        float4* orow = reinterpret_cast<float4*>(outp + (size_t)s * D_FEAT);
        orow[tx] = o;
    }
}

extern "C" void kernel_launch(void* const* d_in, const int* in_sizes, int n_in,
                              void* d_out, int out_size)
{
    const float* x      = (const float*)d_in[0];
    const int*   mask   = (const int*)d_in[1];
    const float* w_obj  = (const float*)d_in[2];
    const float* b_obj  = (const float*)d_in[3];
    const float* w_road = (const float*)d_in[4];
    const float* b_road = (const float*)d_in[5];
    float* out = (float*)d_out;

    cudaFuncSetAttribute(cross_set_norm_kernel,
                         cudaFuncAttributeMaxDynamicSharedMemorySize, SMEM_BYTES);

    dim3 grid(B_TOT * 8);   // b * (2 segs) * (4 feature quarters)
    dim3 block(NTHREADS);
    cross_set_norm_kernel<<<grid, block, SMEM_BYTES>>>(
        x, mask, w_obj, b_obj, w_road, b_road, out);
}